// round 9
// baseline (speedup 1.0000x reference)
#include <cuda_runtime.h>
#include <cuda_bf16.h>
#include <math.h>

// Problem constants (T=256, B=256, I=H=512)
#define TT 256
#define BB 256
#define KK 512          // u32 words per split row (hi/lo pair words)
#define HH 512
#define G3 1536
#define LN_EPS 1e-5f
#define APITCH 520      // resident A tile row pitch (words) — conflict-free LDS.64

// Scratch (static device globals — allocation-free)
__device__ float    g_gi[(size_t)TT * BB * G3];   // (T*B, 3H) input projections
__device__ float    g_gh[2 * (size_t)BB * G3];    // parity-buffered hidden proj
__device__ float    g_h [2 * (size_t)BB * HH];    // parity-buffered fp32 h
__device__ unsigned g_xs [(size_t)TT * BB * KK];  // x split (bf16 hi/lo words)
__device__ unsigned g_wis[(size_t)G3 * KK];       // W_ih split
__device__ unsigned g_whs[(size_t)G3 * KK];       // W_hh split
__device__ unsigned g_hs [(size_t)BB * KK];       // h0 split (t=0 A source)

// ---------------------------------------------------------------------------
// bf16 split helpers. word(2p)=hi bf16x2 of pair p, word(2p+1)=lo bf16x2.
// ---------------------------------------------------------------------------
__device__ __forceinline__ uint2 split2(float x, float y) {
    __nv_bfloat16 hx = __float2bfloat16(x);
    __nv_bfloat16 hy = __float2bfloat16(y);
    __nv_bfloat16 lx = __float2bfloat16(x - __bfloat162float(hx));
    __nv_bfloat16 ly = __float2bfloat16(y - __bfloat162float(hy));
    __nv_bfloat162 hp; hp.x = hx; hp.y = hy;
    __nv_bfloat162 lp; lp.x = lx; lp.y = ly;
    uint2 o;
    o.x = *reinterpret_cast<unsigned*>(&hp);
    o.y = *reinterpret_cast<unsigned*>(&lp);
    return o;
}

__global__ void split_pairs(const float* __restrict__ src,
                            unsigned* __restrict__ dst, int npairs) {
    int i = blockIdx.x * 256 + threadIdx.x;
    if (i >= npairs) return;
    float2 v = ((const float2*)src)[i];
    ((uint2*)dst)[i] = split2(v.x, v.y);
}

__device__ __forceinline__ void mma_bf16(float* d, unsigned a0, unsigned a1,
                                         unsigned a2, unsigned a3,
                                         unsigned b0, unsigned b1) {
    asm volatile(
        "mma.sync.aligned.m16n8k16.row.col.f32.bf16.bf16.f32 "
        "{%0,%1,%2,%3},{%4,%5,%6,%7},{%8,%9},{%0,%1,%2,%3};"
        : "+f"(d[0]), "+f"(d[1]), "+f"(d[2]), "+f"(d[3])
        : "r"(a0), "r"(a1), "r"(a2), "r"(a3), "r"(b0), "r"(b1));
}

// ---------------------------------------------------------------------------
// gi GEMM (phase 1, fully parallel) — proven R7/R8 kernel, 64x64 tile.
// ---------------------------------------------------------------------------
__global__ __launch_bounds__(256) void gemm_bf16s(
    const unsigned* __restrict__ A, const unsigned* __restrict__ W,
    const float* __restrict__ bias, float* __restrict__ C, int ldc)
{
    __shared__ unsigned sA[2][64 * 24];
    __shared__ unsigned sW[2][64 * 24];

    const int tid  = threadIdx.x;
    const int wid  = tid >> 5;
    const int lane = tid & 31;
    const int qr   = lane >> 2;
    const int qc   = lane & 3;
    const int m0   = blockIdx.y * 64;
    const int n0   = blockIdx.x * 64;
    const int m_off = (wid >> 2) * 32;
    const int n_off = (wid & 3) * 16;

    const int srow = tid >> 2;
    const int sq   = tid & 3;
    const int ws0  = 2 * ((2 * sq) & 3) + ((2 * sq) >> 2);
    const int ws1  = 2 * ((2 * sq + 1) & 3) + ((2 * sq + 1) >> 2);
    const unsigned* Wp = W + (size_t)(n0 + srow) * KK + sq * 4;
    const unsigned* Ap = A + (size_t)(m0 + srow) * KK + sq * 4;

    float acc[2][2][4];
    #pragma unroll
    for (int mt = 0; mt < 2; mt++)
        #pragma unroll
        for (int nt = 0; nt < 2; nt++)
            #pragma unroll
            for (int c = 0; c < 4; c++) acc[mt][nt][c] = 0.0f;

    {
        uint4 wv = *(const uint4*)Wp;
        uint4 av = *(const uint4*)Ap;
        sW[0][srow * 24 + ws0]     = wv.x;
        sW[0][srow * 24 + 8 + ws0] = wv.y;
        sW[0][srow * 24 + ws1]     = wv.z;
        sW[0][srow * 24 + 8 + ws1] = wv.w;
        sA[0][srow * 24 + ws0]     = av.x;
        sA[0][srow * 24 + 8 + ws0] = av.y;
        sA[0][srow * 24 + ws1]     = av.z;
        sA[0][srow * 24 + 8 + ws1] = av.w;
    }
    __syncthreads();

    uint4 wnx, anx;
    for (int ch = 0; ch < 32; ++ch) {
        const int cur = ch & 1;
        if (ch < 31) {
            wnx = *(const uint4*)(Wp + (ch + 1) * 16);
            anx = *(const uint4*)(Ap + (ch + 1) * 16);
        }

        const unsigned* pA = sA[cur];
        const unsigned* pW = sW[cur];
        unsigned ah[2][4], al[2][4];
        #pragma unroll
        for (int mt = 0; mt < 2; mt++) {
            const int r = m_off + mt * 16 + qr;
            uint2 h0 = *(const uint2*)(pA + r * 24 + 2 * qc);
            uint2 h1 = *(const uint2*)(pA + (r + 8) * 24 + 2 * qc);
            uint2 l0 = *(const uint2*)(pA + r * 24 + 8 + 2 * qc);
            uint2 l1 = *(const uint2*)(pA + (r + 8) * 24 + 8 + 2 * qc);
            ah[mt][0] = h0.x; ah[mt][1] = h1.x; ah[mt][2] = h0.y; ah[mt][3] = h1.y;
            al[mt][0] = l0.x; al[mt][1] = l1.x; al[mt][2] = l0.y; al[mt][3] = l1.y;
        }
        #pragma unroll
        for (int nt = 0; nt < 2; nt++) {
            const int rn = n_off + nt * 8 + qr;
            uint2 bh = *(const uint2*)(pW + rn * 24 + 2 * qc);
            uint2 bl = *(const uint2*)(pW + rn * 24 + 8 + 2 * qc);
            #pragma unroll
            for (int mt = 0; mt < 2; mt++) {
                mma_bf16(acc[mt][nt], ah[mt][0], ah[mt][1], ah[mt][2], ah[mt][3], bh.x, bh.y);
                mma_bf16(acc[mt][nt], ah[mt][0], ah[mt][1], ah[mt][2], ah[mt][3], bl.x, bl.y);
                mma_bf16(acc[mt][nt], al[mt][0], al[mt][1], al[mt][2], al[mt][3], bh.x, bh.y);
            }
        }

        if (ch < 31) {
            const int nb = cur ^ 1;
            sW[nb][srow * 24 + ws0]     = wnx.x;
            sW[nb][srow * 24 + 8 + ws0] = wnx.y;
            sW[nb][srow * 24 + ws1]     = wnx.z;
            sW[nb][srow * 24 + 8 + ws1] = wnx.w;
            sA[nb][srow * 24 + ws0]     = anx.x;
            sA[nb][srow * 24 + 8 + ws0] = anx.y;
            sA[nb][srow * 24 + ws1]     = anx.z;
            sA[nb][srow * 24 + 8 + ws1] = anx.w;
        }
        __syncthreads();
    }

    #pragma unroll
    for (int mt = 0; mt < 2; mt++)
        #pragma unroll
        for (int nt = 0; nt < 2; nt++) {
            const int r = m0 + m_off + mt * 16 + qr;
            const int c = n0 + n_off + nt * 8 + qc * 2;
            const float bx = bias[c], by = bias[c + 1];
            *(float2*)(C + (size_t)r * ldc + c) =
                make_float2(acc[mt][nt][0] + bx, acc[mt][nt][1] + by);
            *(float2*)(C + (size_t)(r + 8) * ldc + c) =
                make_float2(acc[mt][nt][2] + bx, acc[mt][nt][3] + by);
        }
}

// ---------------------------------------------------------------------------
// Fused step kernel (one launch per timestep).
// Block = 16 m-rows x 128 n-cols. Grid (12, 16) = 192 blocks, 256 threads.
// Phase 1 (t>0): recompute gate(t-1) for this block's 16 rows from gh(t-1),
//   gi(t-1), h(t-2) -> write split-bf16 A tile (masked by mask(t)) into SMEM.
//   bn==0 blocks also write h(t-1) (parity buffer) and y(t-1) with LayerNorm.
//   (t==0: A tile staged from pre-split h0, masked by mask(0).)
// Phase 2: GEMM gh(t) tile = A @ W_hh^T + b_hh. A resident; W streamed in
//   k32 chunks with register prefetch (one __syncthreads per chunk).
// ---------------------------------------------------------------------------
__global__ __launch_bounds__(256, 2) void fused_step(
    int t, const float* __restrict__ masks, const float* __restrict__ b_hh,
    const float* __restrict__ ln_w, const float* __restrict__ ln_b,
    float* __restrict__ y,
    const float* __restrict__ gh_prev, float* __restrict__ gh_out,
    const float* __restrict__ h_prev,  float* __restrict__ h_out)
{
    extern __shared__ unsigned dsm[];
    unsigned* sA = dsm;                      // [16][APITCH]
    unsigned* sWb = dsm + 16 * APITCH;       // [2 buf][2 sub][128*24]

    const int tid  = threadIdx.x;
    const int wid  = tid >> 5;
    const int lane = tid & 31;
    const int qr   = lane >> 2;
    const int qc   = lane & 3;
    const int bn   = blockIdx.x;             // 0..11
    const int bm   = blockIdx.y;             // 0..15
    const int m0   = bm * 16;
    const int n0   = bn * 128;

    // ---- W chunk-0 staging (issued first to overlap with gate) ----
    const int wr = tid >> 1;                 // 0..127 W row
    const int q2 = tid & 1;
    const unsigned* Wrow = g_whs + (size_t)(n0 + wr) * KK;
    {
        #pragma unroll
        for (int sub = 0; sub < 2; sub++) {
            uint4 v0 = *(const uint4*)(Wrow + sub * 16 + 8 * q2);
            uint4 v1 = *(const uint4*)(Wrow + sub * 16 + 8 * q2 + 4);
            unsigned* d = sWb + sub * (128 * 24) + wr * 24;
            d[0 + q2]     = v0.x; d[8 + 0 + q2] = v0.y;   // e=0 -> slot q2
            d[2 + q2]     = v0.z; d[8 + 2 + q2] = v0.w;   // e=1 -> slot 2+q2
            d[4 + q2]     = v1.x; d[8 + 4 + q2] = v1.y;   // e=2
            d[6 + q2]     = v1.z; d[8 + 6 + q2] = v1.w;   // e=3
        }
    }

    // ---- Phase 1: gate / A staging ----
    const int grow = tid >> 4;               // 0..15 local row
    const int gl   = tid & 15;
    const int r    = m0 + grow;              // global batch row

    if (t > 0) {
        const float mprev = __ldg(masks + (t - 1) * BB + r);
        const float mcur  = __ldg(masks + t * BB + r);
        const float* gi  = g_gi + (size_t)((t - 1) * BB + r) * G3;
        const float* ghp = gh_prev + (size_t)r * G3;
        const float* hpp = h_prev + (size_t)r * HH;

        float2 hv[16];
        float s1 = 0.f, s2 = 0.f;
        #pragma unroll
        for (int i = 0; i < 16; i++) {
            const int j = 2 * gl + 32 * i;
            float2 gir = *(const float2*)(gi + j);
            float2 giz = *(const float2*)(gi + HH + j);
            float2 gin = *(const float2*)(gi + 2 * HH + j);
            float2 ghr = __ldcg((const float2*)(ghp + j));
            float2 ghz = __ldcg((const float2*)(ghp + HH + j));
            float2 ghn = __ldcg((const float2*)(ghp + 2 * HH + j));
            float2 hp2 = __ldcg((const float2*)(hpp + j));
            const float r0 = 1.f / (1.f + expf(-(gir.x + ghr.x)));
            const float r1 = 1.f / (1.f + expf(-(gir.y + ghr.y)));
            const float z0 = 1.f / (1.f + expf(-(giz.x + ghz.x)));
            const float z1 = 1.f / (1.f + expf(-(giz.y + ghz.y)));
            const float n0f = tanhf(gin.x + r0 * ghn.x);
            const float n1f = tanhf(gin.y + r1 * ghn.y);
            const float h0 = (1.f - z0) * n0f + z0 * (hp2.x * mprev);
            const float h1 = (1.f - z1) * n1f + z1 * (hp2.y * mprev);
            hv[i] = make_float2(h0, h1);
            s1 += h0 + h1; s2 += h0 * h0 + h1 * h1;

            // split (masked for this step's GEMM) into resident A tile
            uint2 sp = split2(h0 * mcur, h1 * mcur);
            const int p  = gl + 16 * i;      // pair index 0..255
            const int c16 = p >> 3;
            const int j8  = p & 7;
            const int s   = 2 * (j8 & 3) + (j8 >> 2);
            sA[grow * APITCH + c16 * 16 + s]     = sp.x;
            sA[grow * APITCH + c16 * 16 + 8 + s] = sp.y;

            if (bn == 0)
                *(float2*)(h_out + (size_t)r * HH + j) = make_float2(h0, h1);
        }
        // per-row reduction over the 16 lanes of this row
        #pragma unroll
        for (int o = 8; o > 0; o >>= 1) {
            s1 += __shfl_xor_sync(0xFFFFFFFFu, s1, o);
            s2 += __shfl_xor_sync(0xFFFFFFFFu, s2, o);
        }
        if (bn == 0) {
            const float mu   = s1 * (1.f / HH);
            const float rstd = rsqrtf(s2 * (1.f / HH) - mu * mu + LN_EPS);
            float* yp = y + ((size_t)(t - 1) * BB + r) * HH;
            #pragma unroll
            for (int i = 0; i < 16; i++) {
                const int j = 2 * gl + 32 * i;
                float2 w  = *(const float2*)(ln_w + j);
                float2 bb = *(const float2*)(ln_b + j);
                *(float2*)(yp + j) =
                    make_float2((hv[i].x - mu) * rstd * w.x + bb.x,
                                (hv[i].y - mu) * rstd * w.y + bb.y);
            }
        }
    } else {
        // t == 0: A = split(h0) masked by mask(0)
        const unsigned mz = (__ldg(masks + r) != 0.0f) ? 0xFFFFFFFFu : 0u;
        #pragma unroll
        for (int i = 0; i < 16; i++) {
            const int p = gl + 16 * i;
            uint2 v = *(const uint2*)(g_hs + (size_t)r * KK + 2 * p);
            const int c16 = p >> 3;
            const int j8  = p & 7;
            const int s   = 2 * (j8 & 3) + (j8 >> 2);
            sA[grow * APITCH + c16 * 16 + s]     = v.x & mz;
            sA[grow * APITCH + c16 * 16 + 8 + s] = v.y & mz;
        }
    }
    __syncthreads();

    // ---- Phase 2: GEMM gh(t) = A @ W_hh^T + b_hh ----
    float acc[2][4];
    #pragma unroll
    for (int nt = 0; nt < 2; nt++)
        #pragma unroll
        for (int c = 0; c < 4; c++) acc[nt][c] = 0.0f;

    uint4 wpre[4];
    for (int ch = 0; ch < 16; ++ch) {
        const int buf = ch & 1;
        if (ch < 15) {
            const unsigned* src = Wrow + (ch + 1) * 32;
            wpre[0] = *(const uint4*)(src + 8 * q2);
            wpre[1] = *(const uint4*)(src + 8 * q2 + 4);
            wpre[2] = *(const uint4*)(src + 16 + 8 * q2);
            wpre[3] = *(const uint4*)(src + 16 + 8 * q2 + 4);
        }

        #pragma unroll
        for (int sub = 0; sub < 2; sub++) {
            const int c16 = ch * 2 + sub;
            const unsigned* pA = sA + c16 * 16;
            uint2 h0 = *(const uint2*)(pA + qr * APITCH + 2 * qc);
            uint2 h1 = *(const uint2*)(pA + (qr + 8) * APITCH + 2 * qc);
            uint2 l0 = *(const uint2*)(pA + qr * APITCH + 8 + 2 * qc);
            uint2 l1 = *(const uint2*)(pA + (qr + 8) * APITCH + 8 + 2 * qc);
            const unsigned* pW = sWb + (buf * 2 + sub) * (128 * 24);
            #pragma unroll
            for (int nt = 0; nt < 2; nt++) {
                const int rn = wid * 16 + nt * 8 + qr;
                uint2 bh = *(const uint2*)(pW + rn * 24 + 2 * qc);
                uint2 bl = *(const uint2*)(pW + rn * 24 + 8 + 2 * qc);
                mma_bf16(acc[nt], h0.x, h1.x, h0.y, h1.y, bh.x, bh.y);
                mma_bf16(acc[nt], h0.x, h1.x, h0.y, h1.y, bl.x, bl.y);
                mma_bf16(acc[nt], l0.x, l1.x, l0.y, l1.y, bh.x, bh.y);
            }
        }

        if (ch < 15) {
            const int nb = buf ^ 1;
            #pragma unroll
            for (int sub = 0; sub < 2; sub++) {
                unsigned* d = sWb + (nb * 2 + sub) * (128 * 24) + wr * 24;
                uint4 v0 = wpre[sub * 2], v1 = wpre[sub * 2 + 1];
                d[0 + q2] = v0.x; d[8 + 0 + q2] = v0.y;
                d[2 + q2] = v0.z; d[8 + 2 + q2] = v0.w;
                d[4 + q2] = v1.x; d[8 + 4 + q2] = v1.y;
                d[6 + q2] = v1.z; d[8 + 6 + q2] = v1.w;
            }
        }
        __syncthreads();
    }

    // epilogue: write gh(t) tile (+ b_hh)
    #pragma unroll
    for (int nt = 0; nt < 2; nt++) {
        const int c = n0 + wid * 16 + nt * 8 + 2 * qc;
        const float bx = b_hh[c], by = b_hh[c + 1];
        *(float2*)(gh_out + (size_t)(m0 + qr) * G3 + c) =
            make_float2(acc[nt][0] + bx, acc[nt][1] + by);
        *(float2*)(gh_out + (size_t)(m0 + qr + 8) * G3 + c) =
            make_float2(acc[nt][2] + bx, acc[nt][3] + by);
    }
}

// ---------------------------------------------------------------------------
// Final gate (t=255 output): gates + h update + LayerNorm, one block per row.
// ---------------------------------------------------------------------------
__global__ __launch_bounds__(256) void final_gate(
    const float* __restrict__ masks, const float* __restrict__ ln_w,
    const float* __restrict__ ln_b, float* __restrict__ y,
    const float* __restrict__ gh, const float* __restrict__ h_prev,
    float* __restrict__ h_out)
{
    __shared__ float red1[8], red2[8], stat[2];
    const int b   = blockIdx.x;
    const int tid = threadIdx.x;
    const int j   = tid * 2;
    const int t   = TT - 1;

    const float m = masks[t * BB + b];
    const float* gi  = g_gi + (size_t)(t * BB + b) * G3;
    const float* ghp = gh + (size_t)b * G3;

    float2 hv  = *(const float2*)(h_prev + (size_t)b * HH + j);
    float2 gir = *(const float2*)(gi + j);
    float2 giz = *(const float2*)(gi + HH + j);
    float2 gin = *(const float2*)(gi + 2 * HH + j);
    float2 ghr = *(const float2*)(ghp + j);
    float2 ghz = *(const float2*)(ghp + HH + j);
    float2 ghn = *(const float2*)(ghp + 2 * HH + j);

    const float r0 = 1.f / (1.f + expf(-(gir.x + ghr.x)));
    const float r1 = 1.f / (1.f + expf(-(gir.y + ghr.y)));
    const float z0 = 1.f / (1.f + expf(-(giz.x + ghz.x)));
    const float z1 = 1.f / (1.f + expf(-(giz.y + ghz.y)));
    const float n0 = tanhf(gin.x + r0 * ghn.x);
    const float n1 = tanhf(gin.y + r1 * ghn.y);
    const float h0 = (1.f - z0) * n0 + z0 * (hv.x * m);
    const float h1 = (1.f - z1) * n1 + z1 * (hv.y * m);

    *(float2*)(h_out + (size_t)b * HH + j) = make_float2(h0, h1);

    float s1 = h0 + h1, s2 = h0 * h0 + h1 * h1;
    #pragma unroll
    for (int o = 16; o > 0; o >>= 1) {
        s1 += __shfl_xor_sync(0xFFFFFFFFu, s1, o);
        s2 += __shfl_xor_sync(0xFFFFFFFFu, s2, o);
    }
    const int warp = tid >> 5, lane = tid & 31;
    if (lane == 0) { red1[warp] = s1; red2[warp] = s2; }
    __syncthreads();
    if (warp == 0) {
        s1 = (lane < 8) ? red1[lane] : 0.0f;
        s2 = (lane < 8) ? red2[lane] : 0.0f;
        #pragma unroll
        for (int o = 4; o > 0; o >>= 1) {
            s1 += __shfl_xor_sync(0xFFFFFFFFu, s1, o);
            s2 += __shfl_xor_sync(0xFFFFFFFFu, s2, o);
        }
        if (lane == 0) {
            const float mu = s1 * (1.0f / HH);
            stat[0] = mu;
            stat[1] = rsqrtf(s2 * (1.0f / HH) - mu * mu + LN_EPS);
        }
    }
    __syncthreads();

    const float mu = stat[0], rstd = stat[1];
    float2 w  = *(const float2*)(ln_w + j);
    float2 bb = *(const float2*)(ln_b + j);
    *(float2*)(y + (size_t)(t * BB + b) * HH + j) =
        make_float2((h0 - mu) * rstd * w.x + bb.x,
                    (h1 - mu) * rstd * w.y + bb.y);
}

// ---------------------------------------------------------------------------
extern "C" void kernel_launch(void* const* d_in, const int* in_sizes, int n_in,
                              void* d_out, int out_size)
{
    const float* x     = (const float*)d_in[0];
    const float* h0    = (const float*)d_in[1];
    const float* masks = (const float*)d_in[2];
    const float* W_ih  = (const float*)d_in[3];
    const float* W_hh  = (const float*)d_in[4];
    const float* b_ih  = (const float*)d_in[5];
    const float* b_hh  = (const float*)d_in[6];
    const float* ln_w  = (const float*)d_in[7];
    const float* ln_b  = (const float*)d_in[8];

    float* y  = (float*)d_out;
    float* hT = y + (size_t)TT * BB * HH;

    float *gi_p, *gh_p, *h_p;
    unsigned *xs_p, *wis_p, *whs_p, *hs_p;
    cudaGetSymbolAddress((void**)&gi_p,  g_gi);
    cudaGetSymbolAddress((void**)&gh_p,  g_gh);
    cudaGetSymbolAddress((void**)&h_p,   g_h);
    cudaGetSymbolAddress((void**)&xs_p,  g_xs);
    cudaGetSymbolAddress((void**)&wis_p, g_wis);
    cudaGetSymbolAddress((void**)&whs_p, g_whs);
    cudaGetSymbolAddress((void**)&hs_p,  g_hs);

    const size_t BBG3 = (size_t)BB * G3;
    const size_t BBHH = (size_t)BB * HH;

    const int smem_bytes = (16 * APITCH + 2 * 2 * 128 * 24) * (int)sizeof(unsigned);
    cudaFuncSetAttribute(fused_step,
                         cudaFuncAttributeMaxDynamicSharedMemorySize, smem_bytes);

    // Phase 0: one-time bf16 hi/lo splits
    const int npx = TT * BB * KK / 2;
    const int npw = G3 * KK / 2;
    const int nph = BB * HH / 2;
    split_pairs<<<(npx + 255) / 256, 256>>>(x,    xs_p,  npx);
    split_pairs<<<(npw + 255) / 256, 256>>>(W_ih, wis_p, npw);
    split_pairs<<<(npw + 255) / 256, 256>>>(W_hh, whs_p, npw);
    split_pairs<<<(nph + 255) / 256, 256>>>(h0,   hs_p,  nph);
    // seed h(-1) = h0 into parity buffer 1
    cudaMemcpyAsync(h_p + BBHH, h0, BBHH * sizeof(float),
                    cudaMemcpyDeviceToDevice);

    // Phase 1: gi = x @ W_ih^T + b_ih (fully parallel)
    gemm_bf16s<<<dim3(G3 / 64, (TT * BB) / 64), 256>>>(xs_p, wis_p, b_ih, gi_p, G3);

    // Phase 2: fused recurrence — ONE kernel per step
    for (int t = 0; t < TT; t++) {
        fused_step<<<dim3(12, 16), 256, smem_bytes>>>(
            t, masks, b_hh, ln_w, ln_b, y,
            gh_p + ((t + 1) & 1) * BBG3,   // gh(t-1)
            gh_p + (t & 1) * BBG3,         // gh(t) out
            h_p  + (t & 1) * BBHH,         // h(t-2)
            h_p  + ((t + 1) & 1) * BBHH);  // h(t-1) out
    }

    // Final gate: h(255), y(255)
    final_gate<<<BB, 256>>>(masks, ln_w, ln_b, y,
                            gh_p + 1 * BBG3,   // gh(255) (255&1 == 1)
                            h_p  + 0 * BBHH,   // h(254)  (256&1 == 0)
                            h_p  + 1 * BBHH);  // h(255) out

    // hT output
    cudaMemcpyAsync(hT, h_p + BBHH, BBHH * sizeof(float),
                    cudaMemcpyDeviceToDevice);
}

// round 10
// speedup vs baseline: 2.0825x; 2.0825x over previous
#include <cuda_runtime.h>
#include <cuda_bf16.h>
#include <math.h>

// Problem constants (T=256, B=256, I=H=512)
#define TT 256
#define BB 256
#define KK 512          // u32 words per split row (hi/lo pair words)
#define HH 512
#define G3 1536
#define LN_EPS 1e-5f

// Scratch (static device globals — allocation-free)
__device__ float    g_gi[(size_t)TT * BB * G3];  // (T*B, 3H) input projections
__device__ float    g_gh[(size_t)BB * G3];       // (B, 3H) per-step hidden proj
__device__ float    g_h [(size_t)BB * HH];       // (B, H) fp32 hidden state
__device__ unsigned g_xs [(size_t)TT * BB * KK]; // x split (bf16 hi/lo words)
__device__ unsigned g_wis[(size_t)G3 * KK];      // W_ih split
__device__ unsigned g_whs[(size_t)G3 * KK];      // W_hh split
__device__ unsigned g_hs [(size_t)BB * KK];      // h split (updated each step)

// PDL primitives (no-ops when the kernel is launched without the PDL attr)
__device__ __forceinline__ void pdl_wait()    { asm volatile("griddepcontrol.wait;" ::: "memory"); }
__device__ __forceinline__ void pdl_trigger() { asm volatile("griddepcontrol.launch_dependents;" ::: "memory"); }

// ---------------------------------------------------------------------------
// bf16 split helpers. word(2p)=hi bf16x2 of elem pair p, word(2p+1)=lo.
// ---------------------------------------------------------------------------
__device__ __forceinline__ uint2 split2(float x, float y) {
    __nv_bfloat16 hx = __float2bfloat16(x);
    __nv_bfloat16 hy = __float2bfloat16(y);
    __nv_bfloat16 lx = __float2bfloat16(x - __bfloat162float(hx));
    __nv_bfloat16 ly = __float2bfloat16(y - __bfloat162float(hy));
    __nv_bfloat162 hp; hp.x = hx; hp.y = hy;
    __nv_bfloat162 lp; lp.x = lx; lp.y = ly;
    uint2 o;
    o.x = *reinterpret_cast<unsigned*>(&hp);
    o.y = *reinterpret_cast<unsigned*>(&lp);
    return o;
}

__global__ void split_pairs(const float* __restrict__ src,
                            unsigned* __restrict__ dst, int npairs) {
    int i = blockIdx.x * 256 + threadIdx.x;
    if (i >= npairs) return;
    float2 v = ((const float2*)src)[i];
    ((uint2*)dst)[i] = split2(v.x, v.y);
}

__device__ __forceinline__ void mma_bf16(float* d, unsigned a0, unsigned a1,
                                         unsigned a2, unsigned a3,
                                         unsigned b0, unsigned b1) {
    asm volatile(
        "mma.sync.aligned.m16n8k16.row.col.f32.bf16.bf16.f32 "
        "{%0,%1,%2,%3},{%4,%5,%6,%7},{%8,%9},{%0,%1,%2,%3};"
        : "+f"(d[0]), "+f"(d[1]), "+f"(d[2]), "+f"(d[3])
        : "r"(a0), "r"(a1), "r"(a2), "r"(a3), "r"(b0), "r"(b1));
}

// ---------------------------------------------------------------------------
// Split-bf16 NT GEMM (R7-proven): C[m,n] = sum_k A[m,k]*W[n,k] + bias[n]
// Tile MT x 64, 256 threads, 8 warps 2m x 4n. k-chunk 16, double-buffered,
// permuted smem slots -> conflict-free LDS.64 fragment loads.
// PDL: W chunk-0 staged pre-wait (constant), A touched only after wait.
// ---------------------------------------------------------------------------
template<int MT>
__global__ __launch_bounds__(256, 2) void gemm_bf16s(
    const unsigned* __restrict__ A, const unsigned* __restrict__ W,
    const float* __restrict__ bias, const float* __restrict__ rowScale,
    float* __restrict__ C, int ldc)
{
    constexpr int NMT = MT / 32;
    __shared__ unsigned sA[2][MT * 24];
    __shared__ unsigned sW[2][64 * 24];

    const int tid  = threadIdx.x;
    const int wid  = tid >> 5;
    const int lane = tid & 31;
    const int qr   = lane >> 2;
    const int qc   = lane & 3;
    const int m0   = blockIdx.y * MT;
    const int n0   = blockIdx.x * 64;
    const int m_off = (wid >> 2) * (MT / 2);
    const int n_off = (wid & 3) * 16;

    // W staging: 4 threads/row, 4 words each (pairs j, j+1), j = 2*(tid&3)
    const int wrow = tid >> 2;
    const int wj   = (tid & 3) * 2;
    const int ws0  = 2 * (wj & 3) + (wj >> 2);
    const int ws1  = 2 * ((wj + 1) & 3) + ((wj + 1) >> 2);
    const unsigned* Wp = W + (size_t)(n0 + wrow) * KK + (tid & 3) * 4;

    // A staging
    const unsigned* Ap;
    int arow, as0 = 0;
    if (MT == 64) {
        arow = tid >> 2;
        Ap = A + (size_t)(m0 + arow) * KK + (tid & 3) * 4;
    } else {                       // MT == 32: 8 threads/row, 2 words (pair j)
        arow = tid >> 3;
        const int aj = tid & 7;
        as0 = 2 * (aj & 3) + (aj >> 2);
        Ap = A + (size_t)(m0 + arow) * KK + aj * 2;
    }
    const unsigned mz =
        (rowScale == nullptr || rowScale[m0 + arow] != 0.0f) ? 0xFFFFFFFFu : 0u;

    float acc[NMT][2][4];
    #pragma unroll
    for (int mt = 0; mt < NMT; mt++)
        #pragma unroll
        for (int nt = 0; nt < 2; nt++)
            #pragma unroll
            for (int c = 0; c < 4; c++) acc[mt][nt][c] = 0.0f;

    // stage chunk 0: W before the PDL wait (constant), A after.
    {
        uint4 wv = *(const uint4*)Wp;
        sW[0][wrow * 24 + ws0]     = wv.x;
        sW[0][wrow * 24 + 8 + ws0] = wv.y;
        sW[0][wrow * 24 + ws1]     = wv.z;
        sW[0][wrow * 24 + 8 + ws1] = wv.w;
        pdl_wait();   // predecessor's A (g_hs) now visible
        if (MT == 64) {
            uint4 av = *(const uint4*)Ap;
            sA[0][arow * 24 + ws0]     = av.x & mz;
            sA[0][arow * 24 + 8 + ws0] = av.y & mz;
            sA[0][arow * 24 + ws1]     = av.z & mz;
            sA[0][arow * 24 + 8 + ws1] = av.w & mz;
        } else {
            uint2 av = *(const uint2*)Ap;
            sA[0][arow * 24 + as0]     = av.x & mz;
            sA[0][arow * 24 + 8 + as0] = av.y & mz;
        }
    }
    __syncthreads();

    uint4 wnx, anx4; uint2 anx2;
    for (int ch = 0; ch < 32; ++ch) {
        const int cur = ch & 1;
        if (ch < 31) {
            wnx = *(const uint4*)(Wp + (ch + 1) * 16);
            if (MT == 64) anx4 = *(const uint4*)(Ap + (ch + 1) * 16);
            else          anx2 = *(const uint2*)(Ap + (ch + 1) * 16);
        }

        const unsigned* pA = sA[cur];
        const unsigned* pW = sW[cur];
        unsigned ah[NMT][4], al[NMT][4];
        #pragma unroll
        for (int mt = 0; mt < NMT; mt++) {
            const int r = m_off + mt * 16 + qr;
            uint2 h0 = *(const uint2*)(pA + r * 24 + 2 * qc);
            uint2 h1 = *(const uint2*)(pA + (r + 8) * 24 + 2 * qc);
            uint2 l0 = *(const uint2*)(pA + r * 24 + 8 + 2 * qc);
            uint2 l1 = *(const uint2*)(pA + (r + 8) * 24 + 8 + 2 * qc);
            ah[mt][0] = h0.x; ah[mt][1] = h1.x; ah[mt][2] = h0.y; ah[mt][3] = h1.y;
            al[mt][0] = l0.x; al[mt][1] = l1.x; al[mt][2] = l0.y; al[mt][3] = l1.y;
        }
        #pragma unroll
        for (int nt = 0; nt < 2; nt++) {
            const int rn = n_off + nt * 8 + qr;
            uint2 bh = *(const uint2*)(pW + rn * 24 + 2 * qc);
            uint2 bl = *(const uint2*)(pW + rn * 24 + 8 + 2 * qc);
            #pragma unroll
            for (int mt = 0; mt < NMT; mt++) {
                mma_bf16(acc[mt][nt], ah[mt][0], ah[mt][1], ah[mt][2], ah[mt][3], bh.x, bh.y);
                mma_bf16(acc[mt][nt], ah[mt][0], ah[mt][1], ah[mt][2], ah[mt][3], bl.x, bl.y);
                mma_bf16(acc[mt][nt], al[mt][0], al[mt][1], al[mt][2], al[mt][3], bh.x, bh.y);
            }
        }

        if (ch < 31) {
            const int nb = cur ^ 1;
            sW[nb][wrow * 24 + ws0]     = wnx.x;
            sW[nb][wrow * 24 + 8 + ws0] = wnx.y;
            sW[nb][wrow * 24 + ws1]     = wnx.z;
            sW[nb][wrow * 24 + 8 + ws1] = wnx.w;
            if (MT == 64) {
                sA[nb][arow * 24 + ws0]     = anx4.x & mz;
                sA[nb][arow * 24 + 8 + ws0] = anx4.y & mz;
                sA[nb][arow * 24 + ws1]     = anx4.z & mz;
                sA[nb][arow * 24 + 8 + ws1] = anx4.w & mz;
            } else {
                sA[nb][arow * 24 + as0]     = anx2.x & mz;
                sA[nb][arow * 24 + 8 + as0] = anx2.y & mz;
            }
        }
        __syncthreads();
    }

    #pragma unroll
    for (int mt = 0; mt < NMT; mt++)
        #pragma unroll
        for (int nt = 0; nt < 2; nt++) {
            const int r = m0 + m_off + mt * 16 + qr;
            const int c = n0 + n_off + nt * 8 + qc * 2;
            const float bx = bias[c], by = bias[c + 1];
            *(float2*)(C + (size_t)r * ldc + c) =
                make_float2(acc[mt][nt][0] + bx, acc[mt][nt][1] + by);
            *(float2*)(C + (size_t)(r + 8) * ldc + c) =
                make_float2(acc[mt][nt][2] + bx, acc[mt][nt][3] + by);
        }

    pdl_trigger();   // gh stores issued; dependent gate_ln may launch
}

// ---------------------------------------------------------------------------
// Per-step gates + hidden update + LayerNorm (R7-proven). 256 thr x 2 elems.
// Also writes the split-bf16 h for the next step's GEMM.
// ---------------------------------------------------------------------------
__global__ __launch_bounds__(256) void gate_ln(
    int t, const float* __restrict__ masks,
    const float* __restrict__ ln_w, const float* __restrict__ ln_b,
    float* __restrict__ y)
{
    __shared__ float red1[8];
    __shared__ float red2[8];
    __shared__ float stat[2];

    const int b   = blockIdx.x;
    const int tid = threadIdx.x;
    const int j   = tid * 2;

    const float m = masks[t * BB + b];        // constant input: pre-wait OK
    pdl_wait();                               // gh(t) from predecessor GEMM

    const float* gi = g_gi + ((size_t)t * BB + b) * G3;
    const float* gh = g_gh + (size_t)b * G3;
    float* hp = g_h + (size_t)b * HH;

    float2 hv  = *(float2*)(hp + j);
    float2 gir = *(const float2*)(gi + j);
    float2 giz = *(const float2*)(gi + HH + j);
    float2 gin = *(const float2*)(gi + 2 * HH + j);
    float2 ghr = *(const float2*)(gh + j);
    float2 ghz = *(const float2*)(gh + HH + j);
    float2 ghn = *(const float2*)(gh + 2 * HH + j);

    const float r0 = 1.f / (1.f + expf(-(gir.x + ghr.x)));
    const float r1 = 1.f / (1.f + expf(-(gir.y + ghr.y)));
    const float z0 = 1.f / (1.f + expf(-(giz.x + ghz.x)));
    const float z1 = 1.f / (1.f + expf(-(giz.y + ghz.y)));
    const float n0 = tanhf(gin.x + r0 * ghn.x);
    const float n1 = tanhf(gin.y + r1 * ghn.y);
    const float h0 = (1.f - z0) * n0 + z0 * (hv.x * m);
    const float h1 = (1.f - z1) * n1 + z1 * (hv.y * m);

    *(float2*)(hp + j) = make_float2(h0, h1);
    ((uint2*)g_hs)[(size_t)b * (HH / 2) + tid] = split2(h0, h1);

    float s1 = h0 + h1, s2 = h0 * h0 + h1 * h1;
    #pragma unroll
    for (int o = 16; o > 0; o >>= 1) {
        s1 += __shfl_xor_sync(0xFFFFFFFFu, s1, o);
        s2 += __shfl_xor_sync(0xFFFFFFFFu, s2, o);
    }
    const int warp = tid >> 5, lane = tid & 31;
    if (lane == 0) { red1[warp] = s1; red2[warp] = s2; }
    __syncthreads();
    if (warp == 0) {
        s1 = (lane < 8) ? red1[lane] : 0.0f;
        s2 = (lane < 8) ? red2[lane] : 0.0f;
        #pragma unroll
        for (int o = 4; o > 0; o >>= 1) {
            s1 += __shfl_xor_sync(0xFFFFFFFFu, s1, o);
            s2 += __shfl_xor_sync(0xFFFFFFFFu, s2, o);
        }
        if (lane == 0) {
            const float mu = s1 * (1.0f / HH);
            stat[0] = mu;
            stat[1] = rsqrtf(s2 * (1.0f / HH) - mu * mu + LN_EPS);
        }
    }
    __syncthreads();

    const float mu = stat[0], rstd = stat[1];
    float2 w = *(const float2*)(ln_w + j);
    float2 bta = *(const float2*)(ln_b + j);
    float2 o;
    o.x = (h0 - mu) * rstd * w.x + bta.x;
    o.y = (h1 - mu) * rstd * w.y + bta.y;
    *(float2*)(y + ((size_t)t * BB + b) * HH + j) = o;

    pdl_trigger();   // h/hs stores issued; next step's GEMM may launch
}

// ---------------------------------------------------------------------------
// PDL launch helpers
// ---------------------------------------------------------------------------
template<typename F, typename... Args>
static inline void launch_pdl(F f, dim3 grid, dim3 block, Args... args) {
    cudaLaunchConfig_t cfg = {};
    cfg.gridDim = grid;
    cfg.blockDim = block;
    cfg.dynamicSmemBytes = 0;
    cfg.stream = 0;
    cudaLaunchAttribute attr[1];
    attr[0].id = cudaLaunchAttributeProgrammaticStreamSerialization;
    attr[0].val.programmaticStreamSerializationAllowed = 1;
    cfg.attrs = attr;
    cfg.numAttrs = 1;
    cudaLaunchKernelEx(&cfg, f, args...);
}

// ---------------------------------------------------------------------------
extern "C" void kernel_launch(void* const* d_in, const int* in_sizes, int n_in,
                              void* d_out, int out_size)
{
    const float* x     = (const float*)d_in[0];
    const float* h0    = (const float*)d_in[1];
    const float* masks = (const float*)d_in[2];
    const float* W_ih  = (const float*)d_in[3];
    const float* W_hh  = (const float*)d_in[4];
    const float* b_ih  = (const float*)d_in[5];
    const float* b_hh  = (const float*)d_in[6];
    const float* ln_w  = (const float*)d_in[7];
    const float* ln_b  = (const float*)d_in[8];

    float* y  = (float*)d_out;
    float* hT = y + (size_t)TT * BB * HH;

    float *gi_p, *gh_p, *h_p;
    unsigned *xs_p, *wis_p, *whs_p, *hs_p;
    cudaGetSymbolAddress((void**)&gi_p,  g_gi);
    cudaGetSymbolAddress((void**)&gh_p,  g_gh);
    cudaGetSymbolAddress((void**)&h_p,   g_h);
    cudaGetSymbolAddress((void**)&xs_p,  g_xs);
    cudaGetSymbolAddress((void**)&wis_p, g_wis);
    cudaGetSymbolAddress((void**)&whs_p, g_whs);
    cudaGetSymbolAddress((void**)&hs_p,  g_hs);

    // Phase 0: one-time bf16 hi/lo splits (normal launches)
    const int npx = TT * BB * KK / 2;
    const int npw = G3 * KK / 2;
    const int nph = BB * HH / 2;
    split_pairs<<<(npx + 255) / 256, 256>>>(x,    xs_p,  npx);
    split_pairs<<<(npw + 255) / 256, 256>>>(W_ih, wis_p, npw);
    split_pairs<<<(npw + 255) / 256, 256>>>(W_hh, whs_p, npw);
    split_pairs<<<(nph + 255) / 256, 256>>>(h0,   hs_p,  nph);
    cudaMemcpyAsync(h_p, h0, (size_t)BB * HH * sizeof(float),
                    cudaMemcpyDeviceToDevice);

    // Phase 1: gi = x @ W_ih^T + b_ih (fully parallel, normal launch)
    gemm_bf16s<64><<<dim3(G3 / 64, (TT * BB) / 64), 256>>>(
        xs_p, wis_p, b_ih, (const float*)nullptr, gi_p, G3);

    // Phase 2: sequential recurrence, PDL-chained launches
    for (int t = 0; t < TT; t++) {
        launch_pdl(gemm_bf16s<32>, dim3(G3 / 64, BB / 32), dim3(256),
                   (const unsigned*)hs_p, (const unsigned*)whs_p,
                   b_hh, masks + (size_t)t * BB, gh_p, G3);
        launch_pdl(gate_ln, dim3(BB), dim3(256), t, masks, ln_w, ln_b, y);
    }

    // hT output
    cudaMemcpyAsync(hT, h_p, (size_t)BB * HH * sizeof(float),
                    cudaMemcpyDeviceToDevice);
}